// round 17
// baseline (speedup 1.0000x reference)
#include <cuda_runtime.h>
#include <cuda_fp16.h>
#include <cstdint>

#define ZDIM   128
#define MDIM   8192
#define NB     128
#define MT     32                    // M rows per unit
#define NCTA   296                   // 2 x 148 SMs, one full wave
#define KQ     4                     // K split factor
#define KPU    (MDIM / KQ)           // 2048 K per unit
#define NUNITS ((MDIM / MT) * KQ)    // 1024 work units
#define KT     64                    // K per tile (fp16 tile row = 128B)
#define NITER_U (KPU / KT)           // 32 tiles per unit
#define STAGES 16
#define BT_BYTES   (MT * 128)        // 4 KB fp16 B tile
#define RING_BYTES (STAGES * BT_BYTES)        // 64 KB
#define CM_OFF     RING_BYTES                 // 16 KB partial-C merge buffer
#define FULL_OFF   (RING_BYTES + 16384)
#define EMPTY_OFF  (FULL_OFF + 128)
#define SMEM_DYN   (FULL_OFF + 512)
#define OUT_PLANE  (NB * MDIM)

// eps packed into m16n8k16 B-fragment layout, fp16 (2 MB + 128 KB pad).
// uint4 index: (kc*8 + nP)*32 + lane ; kc = k/16 (0..511), nP = n/16 (0..7)
__device__ __align__(16) __half2 g_epsh[OUT_PLANE / 2 + 65536];
// partial C per unit [u][b*32+m] and partial sumsq per unit [u][m]
__device__ float g_pc[NUNITS * MT * NB / 32 * 32];   // 1024*4096 = 16 MB
__device__ float g_pss[NUNITS * MT];                 // 128 KB

static __device__ __forceinline__ uint32_t smem_u32(const void* p) {
    uint32_t a;
    asm("{ .reg .u64 t; cvta.to.shared.u64 t, %1; cvt.u32.u64 %0, t; }" : "=r"(a) : "l"(p));
    return a;
}

#define MBAR_INIT(a, c)  asm volatile("mbarrier.init.shared.b64 [%0], %1;" :: "r"((uint32_t)(a)), "r"((uint32_t)(c)) : "memory")
#define MBAR_ARRIVE(a)   asm volatile("mbarrier.arrive.shared.b64 _, [%0];" :: "r"((uint32_t)(a)) : "memory")

#define MBAR_WAIT(a, ph) do {                                                      \
    uint32_t _m = (uint32_t)(a), _p = (uint32_t)(ph);                              \
    asm volatile("{\n\t.reg .pred P;\n\t"                                          \
        "WL_%=:\n\t"                                                               \
        "mbarrier.try_wait.parity.acquire.cta.shared::cta.b64 P, [%0], %1, 0x989680;\n\t" \
        "@P bra.uni WD_%=;\n\t"                                                    \
        "bra.uni WL_%=;\n\t"                                                       \
        "WD_%=:\n\t}" :: "r"(_m), "r"(_p) : "memory");                             \
} while (0)

#define LDSM_X4(r, addr) \
    asm volatile("ldmatrix.sync.aligned.m8n8.x4.shared.b16 {%0,%1,%2,%3}, [%4];" \
        : "=r"((r)[0]), "=r"((r)[1]), "=r"((r)[2]), "=r"((r)[3]) : "r"((uint32_t)(addr)))

#define MMA16(d, a, b0, b1) \
    asm volatile("mma.sync.aligned.m16n8k16.row.col.f32.f16.f16.f32 " \
        "{%0,%1,%2,%3}, {%4,%5,%6,%7}, {%8,%9}, {%0,%1,%2,%3};" \
        : "+f"((d)[0]), "+f"((d)[1]), "+f"((d)[2]), "+f"((d)[3]) \
        : "r"((a)[0]), "r"((a)[1]), "r"((a)[2]), "r"((a)[3]), "r"(b0), "r"(b1))

// ---------------------------------------------------------------------------
__global__ void cov_fill(const float* __restrict__ mu, const float* __restrict__ logstd,
                         const float* __restrict__ eps, float* __restrict__ out) {
    int i = blockIdx.x * blockDim.x + threadIdx.x;
    if (i >= OUT_PLANE) return;
    int z = i & (ZDIM - 1);
    out[i] = mu[z];
    out[OUT_PLANE + i] = 2.0f * logstd[z];
    if (i < OUT_PLANE / 2) {
        int q  = i & 3;
        int l  = (i >> 2) & 31;
        int nP = (i >> 7) & 7;
        int kc = i >> 10;
        int n  = (2 * nP + (q >> 1)) * 8 + (l >> 2);
        int k  = kc * 16 + 2 * (l & 3) + 8 * (q & 1);
        g_epsh[i] = __floats2half2_rn(eps[(size_t)n * MDIM + k], eps[(size_t)n * MDIM + k + 1]);
    }
}

// ---------------------------------------------------------------------------
// 296 CTAs x 192 threads, 2 CTAs per SM, one full wave.
// CTA b processes work units b, b+296, b+592, b+888 (unit = M32 x K2048).
// warps 0-3: compute (kpar x nh), M32 x N64, C=64 regs, eps via LDG ring.
// warps 4-5: producers — triple-buffered LDG fp32 B -> cvt fp16 (+sumsq) -> STS.
// Per unit: partial C and partial sumsq written to global scratch.
// ---------------------------------------------------------------------------
__global__ void __launch_bounds__(192, 2) cov_main(
    const float* __restrict__ B, float* __restrict__ out)
{
    extern __shared__ char smem_raw[];
    const uint32_t raw  = smem_u32(smem_raw);
    const uint32_t base = (raw + 1023u) & ~1023u;
    char* basep = smem_raw + (base - raw);
    float* smemC = (float*)(basep + CM_OFF);

    const int tid  = threadIdx.x;
    const int wid  = tid >> 5;
    const int lane = tid & 31;

    if (tid == 0) {
        #pragma unroll
        for (int s = 0; s < STAGES; s++) {
            MBAR_INIT(base + FULL_OFF  + s * 8, 64);   // 64 producer threads
            MBAR_INIT(base + EMPTY_OFF + s * 8, 2);    // lane0 of 2 consuming warps
        }
    }
    __syncthreads();

    const int kpar = wid >> 1;
    const int nh   = wid & 1;
    const int g    = lane >> 2;
    const int tg   = lane & 3;

    // consumer per-lane constants
    const uint32_t rowpat = (uint32_t)((lane & 7) + 8 * ((lane >> 3) & 1));
    const uint32_t swzl   = (uint32_t)(lane & 7) << 4;
    uint32_t aRow[2], colA[4];
    #pragma unroll
    for (int q = 0; q < 2; q++)
        aRow[q] = ((uint32_t)(q * 16) + rowpat) * 128u;
    #pragma unroll
    for (int sk = 0; sk < 4; sk++)
        colA[sk] = ((uint32_t)(sk * 32 + 16 * (lane >> 4))) ^ swzl;

    // producer per-lane constants
    const int rb = (tid - 128) >> 4;              // base row 0..3 (producers)
    const int cc = (tid - 128) & 15;              // 16B fp32 chunk in 256B row

    for (int u = blockIdx.x; u < NUNITS; u += NCTA) {
        const int mtile = u >> 2;
        const int kq    = u & 3;

        if (wid < 4) {
            // ---------------- compute warps ----------------
            float C[2][8][4];
            #pragma unroll
            for (int q = 0; q < 2; q++)
                #pragma unroll
                for (int j = 0; j < 8; j++)
                    #pragma unroll
                    for (int e = 0; e < 4; e++) C[q][j][e] = 0.0f;

            const uint4* epsp = (const uint4*)g_epsh;
            #define EIDX(KC, JP) ((size_t)(((KC) * 8 + nh * 4 + (JP)) * 32 + lane))
            const int kcb = kq * 128;
            uint4 bb0[4], bb1[4];
            {
                const int kc0 = kcb + kpar * 4;
                #pragma unroll
                for (int jp = 0; jp < 4; jp++) bb0[jp] = __ldg(&epsp[EIDX(kc0,     jp)]);
                #pragma unroll
                for (int jp = 0; jp < 4; jp++) bb1[jp] = __ldg(&epsp[EIDX(kc0 + 1, jp)]);
            }

            for (int ti = 0; ti < NITER_U / 2; ti++) {
                const int it = 2 * ti + kpar;
                const int s  = it & (STAGES - 1);
                const int ph = (it >> 4) & 1;
                MBAR_WAIT(base + FULL_OFF + s * 8, ph);
                const uint32_t stg = base + (uint32_t)s * BT_BYTES;
                const int kc0 = kcb + it * 4;
                const int pf[4] = { kc0 + 2, kc0 + 3, kc0 + 8, kc0 + 9 };

                #pragma unroll
                for (int sk = 0; sk < 4; sk++) {
                    uint4* cur = (sk & 1) ? bb1 : bb0;
                    uint32_t a[2][4];
                    #pragma unroll
                    for (int q = 0; q < 2; q++)
                        LDSM_X4(a[q], stg + aRow[q] + colA[sk]);
                    #pragma unroll
                    for (int jp = 0; jp < 4; jp++)
                        #pragma unroll
                        for (int q = 0; q < 2; q++) {
                            MMA16(C[q][2 * jp    ], a[q], cur[jp].x, cur[jp].y);
                            MMA16(C[q][2 * jp + 1], a[q], cur[jp].z, cur[jp].w);
                        }
                    #pragma unroll
                    for (int jp = 0; jp < 4; jp++)
                        cur[jp] = __ldg(&epsp[EIDX(pf[sk], jp)]);
                }
                if (lane == 0) MBAR_ARRIVE(base + EMPTY_OFF + s * 8);
            }
            #undef EIDX

            // merge the two kpar partials into smemC
            __syncthreads();
            if (kpar == 0) {
                #pragma unroll
                for (int q = 0; q < 2; q++)
                    #pragma unroll
                    for (int j = 0; j < 8; j++) {
                        int col = nh * 64 + j * 8 + 2 * tg;
                        int row = q * 16 + g;
                        smemC[(col    ) * 32 + row    ] = C[q][j][0];
                        smemC[(col + 1) * 32 + row    ] = C[q][j][1];
                        smemC[(col    ) * 32 + row + 8] = C[q][j][2];
                        smemC[(col + 1) * 32 + row + 8] = C[q][j][3];
                    }
            }
            __syncthreads();
            if (kpar == 1) {
                #pragma unroll
                for (int q = 0; q < 2; q++)
                    #pragma unroll
                    for (int j = 0; j < 8; j++) {
                        int col = nh * 64 + j * 8 + 2 * tg;
                        int row = q * 16 + g;
                        smemC[(col    ) * 32 + row    ] += C[q][j][0];
                        smemC[(col + 1) * 32 + row    ] += C[q][j][1];
                        smemC[(col    ) * 32 + row + 8] += C[q][j][2];
                        smemC[(col + 1) * 32 + row + 8] += C[q][j][3];
                    }
            }
            __syncthreads();
        } else {
            // ---------------- producer warps (64 threads) ----------------
            const float* gB = B + (size_t)mtile * MT * MDIM + kq * KPU;
            float4 bA[8], bB[8], bC[8];
            float ss[8];
            #pragma unroll
            for (int i = 0; i < 8; i++) ss[i] = 0.0f;

            #define P_HANDLE(IT, BUF) do {                                          \
                const int _it = (IT);                                               \
                const int _s  = _it & (STAGES - 1);                                 \
                const int _ph = ((_it >> 4) & 1) ^ 1;                               \
                MBAR_WAIT(base + EMPTY_OFF + _s * 8, _ph);                          \
                const float* _src = gB + (size_t)_it * KT + cc * 4;                 \
                _Pragma("unroll")                                                   \
                for (int uu = 0; uu < 8; uu++)                                      \
                    (BUF)[uu] = *(const float4*)(_src + (size_t)(rb + 4 * uu) * MDIM); \
            } while (0)

            #define P_FLUSH(JT, BUF) do {                                           \
                const int _jt = (JT);                                               \
                const uint32_t _stgj = base + (uint32_t)(_jt & (STAGES - 1)) * BT_BYTES; \
                _Pragma("unroll")                                                   \
                for (int uu = 0; uu < 8; uu++) {                                    \
                    const int _row = rb + 4 * uu;                                   \
                    float4 _f = (BUF)[uu];                                          \
                    __half2 _h0 = __floats2half2_rn(_f.x, _f.y);                    \
                    __half2 _h1 = __floats2half2_rn(_f.z, _f.w);                    \
                    const uint32_t _a = _stgj + (uint32_t)_row * 128u               \
                        + (((uint32_t)(cc * 8)) ^ ((uint32_t)(_row & 7) << 4));     \
                    asm volatile("st.shared.v2.b32 [%0], {%1, %2};"                 \
                        :: "r"(_a), "r"(*(uint32_t*)&_h0), "r"(*(uint32_t*)&_h1) : "memory"); \
                    ss[uu] = fmaf(_f.x, _f.x, ss[uu]);                              \
                    ss[uu] = fmaf(_f.y, _f.y, ss[uu]);                              \
                    ss[uu] = fmaf(_f.z, _f.z, ss[uu]);                              \
                    ss[uu] = fmaf(_f.w, _f.w, ss[uu]);                              \
                }                                                                   \
                MBAR_ARRIVE(base + FULL_OFF + (_jt & (STAGES - 1)) * 8);            \
            } while (0)

            P_HANDLE(0, bA);
            P_HANDLE(1, bB);
            for (int j = 0; j < (NITER_U - 2) / 3; j++) {   // 10 iters -> F(0..29)
                P_HANDLE(3 * j + 2, bC); P_FLUSH(3 * j,     bA);
                P_HANDLE(3 * j + 3, bA); P_FLUSH(3 * j + 1, bB);
                P_HANDLE(3 * j + 4, bB); P_FLUSH(3 * j + 2, bC);
            }
            P_FLUSH(NITER_U - 2, bA);
            P_FLUSH(NITER_U - 1, bB);
            #undef P_HANDLE
            #undef P_FLUSH

            // partial sumsq -> scratch
            #pragma unroll
            for (int uu = 0; uu < 8; uu++) {
                float v = ss[uu];
                v += __shfl_xor_sync(0xffffffffu, v, 1);
                v += __shfl_xor_sync(0xffffffffu, v, 2);
                v += __shfl_xor_sync(0xffffffffu, v, 4);
                v += __shfl_xor_sync(0xffffffffu, v, 8);
                if (cc == 0) g_pss[u * MT + rb + 4 * uu] = v;
            }
            __syncthreads();   // match consumer syncs (merge phase)
            __syncthreads();
            __syncthreads();
        }

        // dump partial C to scratch (all 192 threads; smemC stable after syncs)
        float* pc = g_pc + (size_t)u * (MT * NB);
        for (int idx = tid; idx < MT * NB; idx += 192)
            pc[idx] = smemC[idx];
        __syncthreads();
    }
}

// ---------------------------------------------------------------------------
// Combine: per m-tile, sum 4 K-quarter partials, apply epilogue.
// ---------------------------------------------------------------------------
__global__ void cov_combine(const float* __restrict__ mu, const float* __restrict__ logstd,
                            float* __restrict__ out) {
    const int mt = blockIdx.x;                   // 0..255
    const int tid = threadIdx.x;                 // 128 threads
    __shared__ float sc_s[MT], mu_s[MT];
    if (tid < MT) {
        const int ub = mt * 4;
        float ssum = g_pss[ub * MT + tid] + g_pss[(ub + 1) * MT + tid]
                   + g_pss[(ub + 2) * MT + tid] + g_pss[(ub + 3) * MT + tid];
        int mg = mt * MT + tid, z = mg & (ZDIM - 1);
        sc_s[tid] = rsqrtf(ssum) * expf(logstd[z]);
        mu_s[tid] = mu[z];
    }
    __syncthreads();
    const float* p0 = g_pc + (size_t)(mt * 4    ) * (MT * NB);
    const float* p1 = g_pc + (size_t)(mt * 4 + 1) * (MT * NB);
    const float* p2 = g_pc + (size_t)(mt * 4 + 2) * (MT * NB);
    const float* p3 = g_pc + (size_t)(mt * 4 + 3) * (MT * NB);
    float* op = out + 2 * (size_t)OUT_PLANE + mt * MT;
    for (int idx = tid; idx < MT * NB; idx += 128) {
        int m = idx & (MT - 1), b = idx >> 5;
        float v = p0[idx] + p1[idx] + p2[idx] + p3[idx];
        op[(size_t)b * MDIM + m] = fmaf(sc_s[m], v, mu_s[m]);
    }
}

extern "C" void kernel_launch(void* const* d_in, const int* in_sizes, int n_in,
                              void* d_out, int out_size) {
    const float* mu     = (const float*)d_in[0];
    const float* logstd = (const float*)d_in[1];
    const float* B      = (const float*)d_in[2];
    const float* eps    = (const float*)d_in[3];
    float* out = (float*)d_out;

    cudaFuncSetAttribute(cov_main, cudaFuncAttributeMaxDynamicSharedMemorySize, SMEM_DYN);

    cov_fill<<<(OUT_PLANE + 511) / 512, 512>>>(mu, logstd, eps, out);
    cov_main<<<NCTA, 192, SMEM_DYN>>>(B, out);
    cov_combine<<<MDIM / MT, 128>>>(mu, logstd, out);
}